// round 5
// baseline (speedup 1.0000x reference)
#include <cuda_runtime.h>
#include <cuda_fp16.h>
#include <cuda_bf16.h>

// Problem constants (shapes fixed by the dataset)
#define MAXN 50000
#define MAXE 800000
#define F 128      // input features
#define H 4        // heads
#define C 32       // channels/head  (H*C == F)

#define SCAN_T 1024
#define SCAN_B ((MAXN + SCAN_T - 1) / SCAN_T)   // 49

// Scratch (device globals; no allocation allowed)
__device__ __half g_xwh[MAXN * F];      // x @ W  quantized to fp16 [N, H*C]
__device__ float g_ai[MAXN * H];        // att·xw first half  (source role)
__device__ float g_aj[MAXN * H];        // att·xw second half (dest role)
__device__ float g_p[MAXE * H];         // exp(leaky(alpha)) per edge
__device__ float g_segsum[MAXN * H];    // softmax denominator per (row, h)
__device__ float g_inv[MAXN * H];       // 0.25 / (segsum + 1e-16)
__device__ int   g_cnt[MAXN];           // in-degree histogram (by col)
__device__ int   g_off[MAXN + 1];       // CSR offsets (by col)
__device__ int   g_cur[MAXN];           // scatter cursors
__device__ int   g_bsum[SCAN_B];        // scan block sums
__device__ int   g_boff[SCAN_B];        // scan block offsets
__device__ int   g_sr[MAXE];            // sorted edge: source row
__device__ float4 g_sw[MAXE];           // sorted edge: folded head weights

// ---------------------------------------------------------------------------
// vector atomic add (sm_90+)
__device__ __forceinline__ void red_add_v4(float* p, float a, float b, float c, float d) {
    asm volatile("red.global.add.v4.f32 [%0], {%1, %2, %3, %4};"
                 :: "l"(p), "f"(a), "f"(b), "f"(c), "f"(d) : "memory");
}

// ---------------------------------------------------------------------------
// init: segsum = 0, cnt = 0
__global__ void k_init(int N) {
    int stride = gridDim.x * blockDim.x;
    int t = blockIdx.x * blockDim.x + threadIdx.x;
    for (int i = t; i < N * H; i += stride) g_segsum[i] = 0.0f;
    for (int i = t; i < N; i += stride) g_cnt[i] = 0;
}

// ---------------------------------------------------------------------------
// GEMM: xw = x @ W. Stores fp16 xw and attention half-dots in the epilogue.
#define BM 64
#define BK 16
__global__ void k_gemm(const float* __restrict__ x, const float* __restrict__ w,
                       const float* __restrict__ att, int N) {
    __shared__ float As[BK][BM];
    __shared__ float Bs[BK][F];
    __shared__ float s_att[H * 2 * C];   // 256 floats
    int tid = threadIdx.x;
    int row0 = blockIdx.x * BM;
    int ty = tid >> 4;        // 0..15 -> 4 rows each
    int tx = tid & 15;        // 0..15 -> 8 cols each

    s_att[tid] = att[tid];    // 256 threads, 256 floats

    int ar = tid >> 2;            // 0..63
    int ak = (tid & 3) * 4;       // 0,4,8,12
    int bk = tid >> 4;            // 0..15
    int bj = (tid & 15) * 8;      // 0..120

    float acc[4][8];
#pragma unroll
    for (int i = 0; i < 4; i++)
#pragma unroll
        for (int j = 0; j < 8; j++) acc[i][j] = 0.0f;

    for (int k0 = 0; k0 < F; k0 += BK) {
        float4 av = make_float4(0.f, 0.f, 0.f, 0.f);
        int grow = row0 + ar;
        if (grow < N) av = *(const float4*)&x[grow * F + k0 + ak];
        As[ak + 0][ar] = av.x;
        As[ak + 1][ar] = av.y;
        As[ak + 2][ar] = av.z;
        As[ak + 3][ar] = av.w;
        float4 b0 = *(const float4*)&w[(k0 + bk) * F + bj];
        float4 b1 = *(const float4*)&w[(k0 + bk) * F + bj + 4];
        *(float4*)&Bs[bk][bj]     = b0;
        *(float4*)&Bs[bk][bj + 4] = b1;
        __syncthreads();

#pragma unroll
        for (int k = 0; k < BK; k++) {
            float a[4], b[8];
#pragma unroll
            for (int i = 0; i < 4; i++) a[i] = As[k][ty * 4 + i];
#pragma unroll
            for (int j = 0; j < 8; j++) b[j] = Bs[k][tx * 8 + j];
#pragma unroll
            for (int i = 0; i < 4; i++)
#pragma unroll
                for (int j = 0; j < 8; j++) acc[i][j] += a[i] * b[j];
        }
        __syncthreads();
    }

    int h  = tx >> 2;             // head for this thread's 8 columns
    int c0 = (tx & 3) * 8;        // channel offset within head
    const float* a1 = &s_att[h * 2 * C];
    const float* a2 = a1 + C;

#pragma unroll
    for (int i = 0; i < 4; i++) {
        int grow = row0 + ty * 4 + i;
        if (grow < N) {
            __half2 h0 = __floats2half2_rn(acc[i][0], acc[i][1]);
            __half2 h1 = __floats2half2_rn(acc[i][2], acc[i][3]);
            __half2 h2 = __floats2half2_rn(acc[i][4], acc[i][5]);
            __half2 h3 = __floats2half2_rn(acc[i][6], acc[i][7]);
            uint4 pk;
            pk.x = *reinterpret_cast<unsigned*>(&h0);
            pk.y = *reinterpret_cast<unsigned*>(&h1);
            pk.z = *reinterpret_cast<unsigned*>(&h2);
            pk.w = *reinterpret_cast<unsigned*>(&h3);
            *(uint4*)&g_xwh[grow * F + tx * 8] = pk;
        }
        float s1 = 0.f, s2 = 0.f;
#pragma unroll
        for (int j = 0; j < 8; j++) {
            float v = acc[i][j];
            s1 += v * a1[c0 + j];
            s2 += v * a2[c0 + j];
        }
        s1 += __shfl_xor_sync(0xffffffffu, s1, 1);
        s1 += __shfl_xor_sync(0xffffffffu, s1, 2);
        s2 += __shfl_xor_sync(0xffffffffu, s2, 1);
        s2 += __shfl_xor_sync(0xffffffffu, s2, 2);
        if ((tx & 3) == 0 && grow < N) {
            g_ai[grow * H + h] = s1;
            g_aj[grow * H + h] = s2;
        }
    }
}

// ---------------------------------------------------------------------------
// per-edge: p = exp(leaky(ai[row] + aj[col])); segsum[row] += p; cnt[col]++
__device__ __forceinline__ float leaky_exp(float a) {
    a = (a >= 0.f) ? a : 0.2f * a;
    return __expf(a);
}

__global__ void k_edge1(const int* __restrict__ ei, int E) {
    int e = blockIdx.x * blockDim.x + threadIdx.x;
    if (e >= E) return;
    int r = ei[e];
    int c = ei[E + e];
    float4 ai = *(const float4*)&g_ai[r * H];
    float4 aj = *(const float4*)&g_aj[c * H];
    float4 p;
    p.x = leaky_exp(ai.x + aj.x);
    p.y = leaky_exp(ai.y + aj.y);
    p.z = leaky_exp(ai.z + aj.z);
    p.w = leaky_exp(ai.w + aj.w);
    *(float4*)&g_p[e * H] = p;
    red_add_v4(&g_segsum[r * H], p.x, p.y, p.z, p.w);
    atomicAdd(&g_cnt[c], 1);
}

// ---------------------------------------------------------------------------
// scanA: per-block reduction of g_cnt -> g_bsum; also computes g_inv
__global__ void k_scanA(int N) {
    int i = blockIdx.x * SCAN_T + threadIdx.x;
    int lane = threadIdx.x & 31, wid = threadIdx.x >> 5;
    int v = (i < N) ? g_cnt[i] : 0;
#pragma unroll
    for (int d = 16; d > 0; d >>= 1) v += __shfl_down_sync(0xffffffffu, v, d);
    __shared__ int sm[32];
    if (lane == 0) sm[wid] = v;
    __syncthreads();
    if (wid == 0) {
        int s = sm[lane];
#pragma unroll
        for (int d = 16; d > 0; d >>= 1) s += __shfl_down_sync(0xffffffffu, s, d);
        if (lane == 0) g_bsum[blockIdx.x] = s;
    }
    // folded k_inv: 0.25/(segsum + eps)
    for (int k = blockIdx.x * SCAN_T + threadIdx.x; k < N * H; k += gridDim.x * SCAN_T)
        g_inv[k] = 0.25f / (g_segsum[k] + 1e-16f);
}

// scanB: exclusive scan of block sums (tiny, single thread)
__global__ void k_scanB() {
    if (threadIdx.x == 0) {
        int acc = 0;
        for (int b = 0; b < SCAN_B; b++) {
            int t = g_bsum[b];
            g_boff[b] = acc;
            acc += t;
        }
    }
}

// scanC: block-level exclusive scan + block offset -> g_off, g_cur
__global__ void k_scanC(int N, int E) {
    int i = blockIdx.x * SCAN_T + threadIdx.x;
    int lane = threadIdx.x & 31, wid = threadIdx.x >> 5;
    int v = (i < N) ? g_cnt[i] : 0;
    int sc = v;
#pragma unroll
    for (int d = 1; d < 32; d <<= 1) {
        int t = __shfl_up_sync(0xffffffffu, sc, d);
        if (lane >= d) sc += t;
    }
    __shared__ int wsum[32];
    if (lane == 31) wsum[wid] = sc;
    __syncthreads();
    if (wid == 0) {
        int ws = wsum[lane];
#pragma unroll
        for (int d = 1; d < 32; d <<= 1) {
            int t = __shfl_up_sync(0xffffffffu, ws, d);
            if (lane >= d) ws += t;
        }
        wsum[lane] = ws;
    }
    __syncthreads();
    int warpoff = (wid > 0) ? wsum[wid - 1] : 0;
    int off = g_boff[blockIdx.x] + warpoff + sc - v;
    if (i < N) {
        g_off[i] = off;
        g_cur[i] = off;
    }
    if (blockIdx.x == 0 && threadIdx.x == 0) g_off[N] = E;
}

// ---------------------------------------------------------------------------
// scatter: sort edges by col; fold softmax weights w_h = p_h * inv[row,h]
__global__ void k_scatter(const int* __restrict__ ei, int E) {
    int e = blockIdx.x * blockDim.x + threadIdx.x;
    if (e >= E) return;
    int r = ei[e];
    int c = ei[E + e];
    float4 p = *(const float4*)&g_p[e * H];
    float4 iv = *(const float4*)&g_inv[r * H];
    float4 w;
    w.x = p.x * iv.x;
    w.y = p.y * iv.y;
    w.z = p.z * iv.z;
    w.w = p.w * iv.w;
    int pos = atomicAdd(&g_cur[c], 1);
    g_sr[pos] = r;
    g_sw[pos] = w;
}

// ---------------------------------------------------------------------------
// aggregation: warp per destination node, atomic-free.
// lanes: eo = lane>>3 (edge slot 0..3), l8 = lane&7 (channel group).
// acc[l8*4..+3] = sum_edges sum_h w_h * xw[r, h*32 + l8*4 ..]
__global__ void k_agg(const float* __restrict__ bias, float* __restrict__ out, int N) {
    int warp = (blockIdx.x * blockDim.x + threadIdx.x) >> 5;
    int lane = threadIdx.x & 31;
    if (warp >= N) return;
    int base = g_off[warp];
    int end  = g_off[warp + 1];
    int eo = lane >> 3, l8 = lane & 7;

    float4 acc = make_float4(0.f, 0.f, 0.f, 0.f);
    for (int i = base + eo; i < end; i += 4) {
        int r = g_sr[i];
        float4 w = g_sw[i];
        const __half* xr = &g_xwh[r * F + l8 * 4];
        uint2 u0 = *(const uint2*)&xr[0];
        uint2 u1 = *(const uint2*)&xr[C];
        uint2 u2 = *(const uint2*)&xr[2 * C];
        uint2 u3 = *(const uint2*)&xr[3 * C];
        float2 v0a = __half22float2(*reinterpret_cast<__half2*>(&u0.x));
        float2 v0b = __half22float2(*reinterpret_cast<__half2*>(&u0.y));
        float2 v1a = __half22float2(*reinterpret_cast<__half2*>(&u1.x));
        float2 v1b = __half22float2(*reinterpret_cast<__half2*>(&u1.y));
        float2 v2a = __half22float2(*reinterpret_cast<__half2*>(&u2.x));
        float2 v2b = __half22float2(*reinterpret_cast<__half2*>(&u2.y));
        float2 v3a = __half22float2(*reinterpret_cast<__half2*>(&u3.x));
        float2 v3b = __half22float2(*reinterpret_cast<__half2*>(&u3.y));
        acc.x += w.x * v0a.x + w.y * v1a.x + w.z * v2a.x + w.w * v3a.x;
        acc.y += w.x * v0a.y + w.y * v1a.y + w.z * v2a.y + w.w * v3a.y;
        acc.z += w.x * v0b.x + w.y * v1b.x + w.z * v2b.x + w.w * v3b.x;
        acc.w += w.x * v0b.y + w.y * v1b.y + w.z * v2b.y + w.w * v3b.y;
    }
    // combine the 4 edge slots (lanes differing in bits 3,4)
    acc.x += __shfl_xor_sync(0xffffffffu, acc.x, 8);
    acc.y += __shfl_xor_sync(0xffffffffu, acc.y, 8);
    acc.z += __shfl_xor_sync(0xffffffffu, acc.z, 8);
    acc.w += __shfl_xor_sync(0xffffffffu, acc.w, 8);
    acc.x += __shfl_xor_sync(0xffffffffu, acc.x, 16);
    acc.y += __shfl_xor_sync(0xffffffffu, acc.y, 16);
    acc.z += __shfl_xor_sync(0xffffffffu, acc.z, 16);
    acc.w += __shfl_xor_sync(0xffffffffu, acc.w, 16);

    if (eo == 0) {
        float4 b = *(const float4*)&bias[l8 * 4];
        acc.x += b.x;
        acc.y += b.y;
        acc.z += b.z;
        acc.w += b.w;
        *(float4*)&out[warp * C + l8 * 4] = acc;
    }
}

// ---------------------------------------------------------------------------
extern "C" void kernel_launch(void* const* d_in, const int* in_sizes, int n_in,
                              void* d_out, int out_size) {
    const float* x    = (const float*)d_in[0];
    const int*   ei   = (const int*)d_in[1];
    const float* w    = (const float*)d_in[2];
    const float* att  = (const float*)d_in[3];
    const float* bias = (const float*)d_in[4];
    float* out = (float*)d_out;

    int N = in_sizes[0] / F;
    int E = in_sizes[1] / 2;

    k_init<<<512, 256>>>(N);
    k_gemm<<<(N + BM - 1) / BM, 256>>>(x, w, att, N);
    k_edge1<<<(E + 255) / 256, 256>>>(ei, E);
    k_scanA<<<SCAN_B, SCAN_T>>>(N);
    k_scanB<<<1, 32>>>();
    k_scanC<<<SCAN_B, SCAN_T>>>(N, E);
    k_scatter<<<(E + 255) / 256, 256>>>(ei, E);
    k_agg<<<(N * 32 + 255) / 256, 256>>>(bias, out, N);
}

// round 6
// speedup vs baseline: 1.1833x; 1.1833x over previous
#include <cuda_runtime.h>
#include <cuda_fp16.h>
#include <cuda_bf16.h>
#include <mma.h>

using namespace nvcuda;

// Problem constants (shapes fixed by the dataset)
#define MAXN 50000
#define MAXE 800000
#define F 128      // input features
#define H 4        // heads
#define C 32       // channels/head  (H*C == F)

// Scratch (device globals; no allocation allowed)
__device__ __half g_xwh[MAXN * F];      // x @ W  quantized to fp16 [N, H*C]
__device__ float g_ai[MAXN * H];        // att·xw first half  (source role)
__device__ float g_aj[MAXN * H];        // att·xw second half (dest role)
__device__ float g_p[MAXE * H];         // exp(leaky(alpha)) per edge
__device__ float g_segsum[MAXN * H];    // softmax denominator per (row, h)
__device__ float g_inv[MAXN * H];       // 0.25 / (segsum + 1e-16)

// ---------------------------------------------------------------------------
// vector atomic add (sm_90+): one red op covers 16 bytes
__device__ __forceinline__ void red_add_v4(float* p, float a, float b, float c, float d) {
    asm volatile("red.global.add.v4.f32 [%0], {%1, %2, %3, %4};"
                 :: "l"(p), "f"(a), "f"(b), "f"(c), "f"(d) : "memory");
}

// ---------------------------------------------------------------------------
// init: segsum = 0, out[n,c] = bias[c]  (atomics accumulate into out directly)
__global__ void k_init(const float* __restrict__ bias, float* __restrict__ out, int N) {
    int stride = gridDim.x * blockDim.x;
    int t = blockIdx.x * blockDim.x + threadIdx.x;
    for (int i = t; i < N * C; i += stride) out[i] = bias[i & (C - 1)];
    for (int i = t; i < N * H; i += stride) g_segsum[i] = 0.0f;
}

// ---------------------------------------------------------------------------
// Tensor-core GEMM: xw = x @ W (fp16 HMMA, fp32 accum).
// Block = 64 rows x 128 cols, 8 warps. K staged in two 64-wide halves.
// Epilogue (via smem round-trip): fp16 xw store + attention half-dots.
#define BM 64
#define LDA 72           // sA leading dim (halfs), mult of 8, padded
// smem layout (bytes):
//   stage:    sA [64*72 half] @ 0 (9216), sB [64*128 half] @ 9216 (16384)
//   epilogue: sC [64*128 float] @ 0 (32768)
//   s_att:    256 floats @ 32768 (1024)   -> total 33792
#define SM_BYTES (32768 + 1024)

__global__ void k_gemm(const float* __restrict__ x, const float* __restrict__ w,
                       const float* __restrict__ att, int N) {
    __shared__ __align__(16) char smbuf[SM_BYTES];
    __half* sA = (__half*)smbuf;
    __half* sB = (__half*)(smbuf + 64 * LDA * 2);
    float*  sC = (float*)smbuf;
    float*  s_att = (float*)(smbuf + 32768);

    int tid = threadIdx.x;
    int row0 = blockIdx.x * BM;
    int warp = tid >> 5;
    int mt = warp & 3;            // m-tile (16 rows)
    int nb = (warp >> 2) * 64;    // n base (64 cols)

    s_att[tid] = att[tid];

    wmma::fragment<wmma::accumulator, 16, 16, 16, float> acc[4];
#pragma unroll
    for (int t = 0; t < 4; t++) wmma::fill_fragment(acc[t], 0.0f);

    int arow = tid >> 2;          // 0..63
    int aq   = (tid & 3) * 16;    // k-offset within stage
    int brow = tid >> 2;          // 0..63 (k index within stage)
    int bs   = (tid & 3) * 32;    // col segment

#pragma unroll
    for (int k0 = 0; k0 < F; k0 += 64) {
        // load A stage: rows 0..63, k = k0..k0+63 (fp32 -> half)
        {
            int grow = row0 + arow;
#pragma unroll
            for (int j = 0; j < 4; j++) {
                float4 v = make_float4(0.f, 0.f, 0.f, 0.f);
                if (grow < N) v = *(const float4*)&x[grow * F + k0 + aq + j * 4];
                __half2 h0 = __floats2half2_rn(v.x, v.y);
                __half2 h1 = __floats2half2_rn(v.z, v.w);
                *(__half2*)&sA[arow * LDA + aq + j * 4]     = h0;
                *(__half2*)&sA[arow * LDA + aq + j * 4 + 2] = h1;
            }
        }
        // load B stage: w rows k0..k0+63, all 128 cols (fp32 -> half)
        {
#pragma unroll
            for (int j = 0; j < 8; j++) {
                float4 v = *(const float4*)&w[(k0 + brow) * F + bs + j * 4];
                __half2 h0 = __floats2half2_rn(v.x, v.y);
                __half2 h1 = __floats2half2_rn(v.z, v.w);
                *(__half2*)&sB[brow * F + bs + j * 4]     = h0;
                *(__half2*)&sB[brow * F + bs + j * 4 + 2] = h1;
            }
        }
        __syncthreads();

#pragma unroll
        for (int kk = 0; kk < 4; kk++) {
            wmma::fragment<wmma::matrix_a, 16, 16, 16, __half, wmma::row_major> fa;
            wmma::load_matrix_sync(fa, &sA[mt * 16 * LDA + kk * 16], LDA);
#pragma unroll
            for (int nt = 0; nt < 4; nt++) {
                wmma::fragment<wmma::matrix_b, 16, 16, 16, __half, wmma::row_major> fb;
                wmma::load_matrix_sync(fb, &sB[kk * 16 * F + nb + nt * 16], F);
                wmma::mma_sync(acc[nt], fa, fb, acc[nt]);
            }
        }
        __syncthreads();
    }

    // dump accumulators to smem (fp32), then epilogue
#pragma unroll
    for (int nt = 0; nt < 4; nt++)
        wmma::store_matrix_sync(&sC[mt * 16 * F + nb + nt * 16], acc[nt], F, wmma::mem_row_major);
    __syncthreads();

    // epilogue: thread t -> (local row = t>>2, head = t&3)
    {
        int lrow = tid >> 2;
        int h = tid & 3;
        int grow = row0 + lrow;
        const float* cr = &sC[lrow * F + h * C];
        const float* a1 = &s_att[h * 2 * C];
        const float* a2 = a1 + C;
        float s1 = 0.f, s2 = 0.f;
        __half hv[C];
#pragma unroll
        for (int j = 0; j < C; j++) {
            float v = cr[j];
            s1 += v * a1[j];
            s2 += v * a2[j];
            hv[j] = __float2half_rn(v);
        }
        if (grow < N) {
            *(uint4*)&g_xwh[grow * F + h * C]      = *(uint4*)&hv[0];
            *(uint4*)&g_xwh[grow * F + h * C + 8]  = *(uint4*)&hv[8];
            *(uint4*)&g_xwh[grow * F + h * C + 16] = *(uint4*)&hv[16];
            *(uint4*)&g_xwh[grow * F + h * C + 24] = *(uint4*)&hv[24];
            g_ai[grow * H + h] = s1;
            g_aj[grow * H + h] = s2;
        }
    }
}

// ---------------------------------------------------------------------------
// per-edge: p = exp(leaky(a_i[row] + a_j[col])); segsum[row] += p (one v4 red)
// (softmax max-shift skipped: shift-invariant, |alpha| small -> no overflow)
__device__ __forceinline__ float leaky_exp(float a) {
    a = (a >= 0.f) ? a : 0.2f * a;
    return __expf(a);
}

__global__ void k_edge1(const int* __restrict__ ei, int E) {
    int e = blockIdx.x * blockDim.x + threadIdx.x;
    if (e >= E) return;
    int r = ei[e];
    int c = ei[E + e];
    float4 ai = *(const float4*)&g_ai[r * H];
    float4 aj = *(const float4*)&g_aj[c * H];
    float4 p;
    p.x = leaky_exp(ai.x + aj.x);
    p.y = leaky_exp(ai.y + aj.y);
    p.z = leaky_exp(ai.z + aj.z);
    p.w = leaky_exp(ai.w + aj.w);
    *(float4*)&g_p[e * H] = p;
    red_add_v4(&g_segsum[r * H], p.x, p.y, p.z, p.w);
}

// ---------------------------------------------------------------------------
// inv[n,h] = 0.25 / (segsum[n,h] + 1e-16)   (folds head-mean factor)
__global__ void k_inv(int N) {
    int t = blockIdx.x * blockDim.x + threadIdx.x;
    if (t >= N * H) return;
    g_inv[t] = 0.25f / (g_segsum[t] + 1e-16f);
}

// ---------------------------------------------------------------------------
// aggregation with head-fold: 8 lanes per edge, TWO edges per 8-lane group
// (front-batched loads double the memory-level parallelism).
// out[col, c] += sum_h w_h * xw[row, h*32 + c]   (c = lane8*4 .. +3)
__device__ __forceinline__ float4 edge_msg(int r, float4 p, int l8) {
    float4 iv = *(const float4*)&g_inv[r * H];
    float w0 = p.x * iv.x;
    float w1 = p.y * iv.y;
    float w2 = p.z * iv.z;
    float w3 = p.w * iv.w;
    const __half* xr = &g_xwh[r * F + l8 * 4];
    uint2 u0 = *(const uint2*)&xr[0];
    uint2 u1 = *(const uint2*)&xr[C];
    uint2 u2 = *(const uint2*)&xr[2 * C];
    uint2 u3 = *(const uint2*)&xr[3 * C];
    float2 v0a = __half22float2(*reinterpret_cast<__half2*>(&u0.x));
    float2 v0b = __half22float2(*reinterpret_cast<__half2*>(&u0.y));
    float2 v1a = __half22float2(*reinterpret_cast<__half2*>(&u1.x));
    float2 v1b = __half22float2(*reinterpret_cast<__half2*>(&u1.y));
    float2 v2a = __half22float2(*reinterpret_cast<__half2*>(&u2.x));
    float2 v2b = __half22float2(*reinterpret_cast<__half2*>(&u2.y));
    float2 v3a = __half22float2(*reinterpret_cast<__half2*>(&u3.x));
    float2 v3b = __half22float2(*reinterpret_cast<__half2*>(&u3.y));
    float4 m;
    m.x = w0 * v0a.x + w1 * v1a.x + w2 * v2a.x + w3 * v3a.x;
    m.y = w0 * v0a.y + w1 * v1a.y + w2 * v2a.y + w3 * v3a.y;
    m.z = w0 * v0b.x + w1 * v1b.x + w2 * v2b.x + w3 * v3b.x;
    m.w = w0 * v0b.y + w1 * v1b.y + w2 * v2b.y + w3 * v3b.y;
    return m;
}

__global__ void k_edge2(const int* __restrict__ ei, float* __restrict__ out, int E) {
    int gt = blockIdx.x * blockDim.x + threadIdx.x;
    int E2 = (E + 1) >> 1;
    int g8 = gt >> 3;
    if (g8 >= E2) return;
    int l8 = gt & 7;
    int e0 = g8;
    int e1 = g8 + E2;
    bool has1 = (e1 < E);
    if (!has1) e1 = e0;

    // front-batched index loads
    int r0 = __ldg(&ei[e0]);
    int c0 = __ldg(&ei[E + e0]);
    int r1 = __ldg(&ei[e1]);
    int c1 = __ldg(&ei[E + e1]);

    float4 p0 = *(const float4*)&g_p[e0 * H];
    float4 p1 = *(const float4*)&g_p[e1 * H];

    float4 m0 = edge_msg(r0, p0, l8);
    float4 m1 = edge_msg(r1, p1, l8);

    red_add_v4(&out[c0 * C + l8 * 4], m0.x, m0.y, m0.z, m0.w);
    if (has1) red_add_v4(&out[c1 * C + l8 * 4], m1.x, m1.y, m1.z, m1.w);
}

// ---------------------------------------------------------------------------
extern "C" void kernel_launch(void* const* d_in, const int* in_sizes, int n_in,
                              void* d_out, int out_size) {
    const float* x    = (const float*)d_in[0];
    const int*   ei   = (const int*)d_in[1];
    const float* w    = (const float*)d_in[2];
    const float* att  = (const float*)d_in[3];
    const float* bias = (const float*)d_in[4];
    float* out = (float*)d_out;

    int N = in_sizes[0] / F;
    int E = in_sizes[1] / 2;
    int E2 = (E + 1) >> 1;

    k_init<<<1024, 256>>>(bias, out, N);
    k_gemm<<<(N + BM - 1) / BM, 256>>>(x, w, att, N);
    k_edge1<<<(E + 255) / 256, 256>>>(ei, E);
    k_inv<<<(N * H + 255) / 256, 256>>>(N);
    k_edge2<<<(E2 * 8 + 255) / 256, 256>>>(ei, out, E);
}

// round 7
// speedup vs baseline: 1.2380x; 1.0462x over previous
#include <cuda_runtime.h>
#include <cuda_fp16.h>
#include <cuda_bf16.h>
#include <mma.h>

using namespace nvcuda;

// Problem constants (shapes fixed by the dataset)
#define MAXN 50000
#define MAXE 800000
#define F 128      // input features
#define H 4        // heads
#define C 32       // channels/head  (H*C == F)

// Scratch (device globals; no allocation allowed)
// g_xwh layout is HEAD-INTERLEAVED: g_xwh[n*128 + c*4 + h]  (c=0..31, h=0..3)
__device__ __half g_xwh[MAXN * F];
__device__ float g_ai[MAXN * H];        // att·xw first half  (source role)
__device__ float g_aj[MAXN * H];        // att·xw second half (dest role)
__device__ float g_p[MAXE * H];         // exp(leaky(alpha)) per edge
__device__ float g_segsum[MAXN * H];    // softmax denominator per (row, h)
__device__ float g_inv[MAXN * H];       // 0.25 / (segsum + 1e-16)

// ---------------------------------------------------------------------------
// vector atomic adds (sm_90+)
__device__ __forceinline__ void red_add_v4(float* p, float a, float b, float c, float d) {
    asm volatile("red.global.add.v4.f32 [%0], {%1, %2, %3, %4};"
                 :: "l"(p), "f"(a), "f"(b), "f"(c), "f"(d) : "memory");
}
__device__ __forceinline__ void red_add_v2(float* p, float a, float b) {
    asm volatile("red.global.add.v2.f32 [%0], {%1, %2};"
                 :: "l"(p), "f"(a), "f"(b) : "memory");
}

// ---------------------------------------------------------------------------
// Tensor-core GEMM: xw = x @ W (fp16 HMMA, fp32 accum).
// Block = 64 rows x 128 cols, 8 warps. Epilogue also:
//   - stores head-interleaved fp16 xw
//   - computes attention half-dots ai/aj
//   - zeroes g_segsum, initializes out = bias   (replaces k_init)
#define BM 64
#define LDA 72           // sA leading dim (halfs), padded
#define SM_BYTES (32768 + 1024)

__global__ void k_gemm(const float* __restrict__ x, const float* __restrict__ w,
                       const float* __restrict__ att, const float* __restrict__ bias,
                       float* __restrict__ out, int N) {
    __shared__ __align__(16) char smbuf[SM_BYTES];
    __half* sA = (__half*)smbuf;
    __half* sB = (__half*)(smbuf + 64 * LDA * 2);
    float*  sC = (float*)smbuf;
    float*  s_att = (float*)(smbuf + 32768);

    int tid = threadIdx.x;
    int row0 = blockIdx.x * BM;
    int warp = tid >> 5;
    int mt = warp & 3;            // m-tile (16 rows)
    int nb = (warp >> 2) * 64;    // n base (64 cols)

    s_att[tid] = att[tid];

    wmma::fragment<wmma::accumulator, 16, 16, 16, float> acc[4];
#pragma unroll
    for (int t = 0; t < 4; t++) wmma::fill_fragment(acc[t], 0.0f);

    int arow = tid >> 2;          // 0..63
    int aq   = (tid & 3) * 16;    // k-offset within stage
    int brow = tid >> 2;          // 0..63 (k index within stage)
    int bs   = (tid & 3) * 32;    // col segment

#pragma unroll
    for (int k0 = 0; k0 < F; k0 += 64) {
        {
            int grow = row0 + arow;
#pragma unroll
            for (int j = 0; j < 4; j++) {
                float4 v = make_float4(0.f, 0.f, 0.f, 0.f);
                if (grow < N) v = *(const float4*)&x[grow * F + k0 + aq + j * 4];
                __half2 h0 = __floats2half2_rn(v.x, v.y);
                __half2 h1 = __floats2half2_rn(v.z, v.w);
                *(__half2*)&sA[arow * LDA + aq + j * 4]     = h0;
                *(__half2*)&sA[arow * LDA + aq + j * 4 + 2] = h1;
            }
        }
        {
#pragma unroll
            for (int j = 0; j < 8; j++) {
                float4 v = *(const float4*)&w[(k0 + brow) * F + bs + j * 4];
                __half2 h0 = __floats2half2_rn(v.x, v.y);
                __half2 h1 = __floats2half2_rn(v.z, v.w);
                *(__half2*)&sB[brow * F + bs + j * 4]     = h0;
                *(__half2*)&sB[brow * F + bs + j * 4 + 2] = h1;
            }
        }
        __syncthreads();

#pragma unroll
        for (int kk = 0; kk < 4; kk++) {
            wmma::fragment<wmma::matrix_a, 16, 16, 16, __half, wmma::row_major> fa;
            wmma::load_matrix_sync(fa, &sA[mt * 16 * LDA + kk * 16], LDA);
#pragma unroll
            for (int nt = 0; nt < 4; nt++) {
                wmma::fragment<wmma::matrix_b, 16, 16, 16, __half, wmma::row_major> fb;
                wmma::load_matrix_sync(fb, &sB[kk * 16 * F + nb + nt * 16], F);
                wmma::mma_sync(acc[nt], fa, fb, acc[nt]);
            }
        }
        __syncthreads();
    }

#pragma unroll
    for (int nt = 0; nt < 4; nt++)
        wmma::store_matrix_sync(&sC[mt * 16 * F + nb + nt * 16], acc[nt], F, wmma::mem_row_major);
    __syncthreads();

    // epilogue: thread t -> (local row = t>>2, channel quarter q = t&3)
    {
        int lrow = tid >> 2;
        int q = tid & 3;
        int grow = row0 + lrow;
        float s1[H], s2[H];
        __half buf[32];
#pragma unroll
        for (int h = 0; h < H; h++) { s1[h] = 0.f; s2[h] = 0.f; }
#pragma unroll
        for (int h = 0; h < H; h++) {
            const float* cr = &sC[lrow * F + h * C + q * 8];
            const float* a1 = &s_att[h * 2 * C + q * 8];
            const float* a2 = a1 + C;
#pragma unroll
            for (int j = 0; j < 8; j++) {
                float v = cr[j];
                s1[h] += v * a1[j];
                s2[h] += v * a2[j];
                buf[j * 4 + h] = __float2half_rn(v);   // interleaved [c][h]
            }
        }
        // butterfly over the 4 q-lanes: elementwise sum per head
#pragma unroll
        for (int h = 0; h < H; h++) {
            s1[h] += __shfl_xor_sync(0xffffffffu, s1[h], 1);
            s1[h] += __shfl_xor_sync(0xffffffffu, s1[h], 2);
            s2[h] += __shfl_xor_sync(0xffffffffu, s2[h], 1);
            s2[h] += __shfl_xor_sync(0xffffffffu, s2[h], 2);
        }
        if (grow < N) {
            // 64B contiguous fp16 store (channels q*8..q*8+7, all heads)
            *(uint4*)&g_xwh[grow * F + q * 32]      = *(uint4*)&buf[0];
            *(uint4*)&g_xwh[grow * F + q * 32 + 8]  = *(uint4*)&buf[8];
            *(uint4*)&g_xwh[grow * F + q * 32 + 16] = *(uint4*)&buf[16];
            *(uint4*)&g_xwh[grow * F + q * 32 + 24] = *(uint4*)&buf[24];
            g_ai[grow * H + q] = s1[q];
            g_aj[grow * H + q] = s2[q];
            g_segsum[grow * H + q] = 0.0f;
            // out = bias  (channels q*8 .. q*8+7)
            float4 b0 = *(const float4*)&bias[q * 8];
            float4 b1 = *(const float4*)&bias[q * 8 + 4];
            *(float4*)&out[grow * C + q * 8]     = b0;
            *(float4*)&out[grow * C + q * 8 + 4] = b1;
        }
    }
}

// ---------------------------------------------------------------------------
// per-edge: p = exp(leaky(a_i[row] + a_j[col])); segsum[row] += p (one v4 red)
// (softmax max-shift skipped: shift-invariant, |alpha| small -> no overflow)
__device__ __forceinline__ float leaky_exp(float a) {
    a = (a >= 0.f) ? a : 0.2f * a;
    return __expf(a);
}

__global__ void k_edge1(const int* __restrict__ ei, int E) {
    int e = blockIdx.x * blockDim.x + threadIdx.x;
    if (e >= E) return;
    int r = ei[e];
    int c = ei[E + e];
    float4 ai = *(const float4*)&g_ai[r * H];
    float4 aj = *(const float4*)&g_aj[c * H];
    float4 p;
    p.x = leaky_exp(ai.x + aj.x);
    p.y = leaky_exp(ai.y + aj.y);
    p.z = leaky_exp(ai.z + aj.z);
    p.w = leaky_exp(ai.w + aj.w);
    *(float4*)&g_p[e * H] = p;
    red_add_v4(&g_segsum[r * H], p.x, p.y, p.z, p.w);
}

// ---------------------------------------------------------------------------
// inv[n,h] = 0.25 / (segsum[n,h] + 1e-16)   (folds head-mean factor)
__global__ void k_inv(int N) {
    int t = blockIdx.x * blockDim.x + threadIdx.x;
    if (t >= N * H) return;
    g_inv[t] = 0.25f / (g_segsum[t] + 1e-16f);
}

// ---------------------------------------------------------------------------
// aggregation: 16 lanes per edge, 2 edges per warp.
// Lane l covers output channels 2l, 2l+1: loads ONE uint4 (16B) of the
// head-interleaved row = {c0:h0..h3, c1:h0..h3}, folds heads, red.v2 out.
__global__ void k_edge2(const int* __restrict__ ei, float* __restrict__ out, int E) {
    int gt = blockIdx.x * blockDim.x + threadIdx.x;
    int e = gt >> 4;
    if (e >= E) return;
    int l = gt & 15;

    int r = __ldg(&ei[e]);
    int c = __ldg(&ei[E + e]);

    float4 p = *(const float4*)&g_p[e * H];
    float4 iv = *(const float4*)&g_inv[r * H];
    float w0 = p.x * iv.x;
    float w1 = p.y * iv.y;
    float w2 = p.z * iv.z;
    float w3 = p.w * iv.w;

    uint4 u = *(const uint4*)&g_xwh[r * F + l * 8];   // 8 halfs, 16B coalesced
    float2 c0a = __half22float2(*reinterpret_cast<__half2*>(&u.x));  // c0: h0,h1
    float2 c0b = __half22float2(*reinterpret_cast<__half2*>(&u.y));  // c0: h2,h3
    float2 c1a = __half22float2(*reinterpret_cast<__half2*>(&u.z));  // c1: h0,h1
    float2 c1b = __half22float2(*reinterpret_cast<__half2*>(&u.w));  // c1: h2,h3

    float m0 = w0 * c0a.x + w1 * c0a.y + w2 * c0b.x + w3 * c0b.y;
    float m1 = w0 * c1a.x + w1 * c1a.y + w2 * c1b.x + w3 * c1b.y;

    red_add_v2(&out[c * C + l * 2], m0, m1);
}

// ---------------------------------------------------------------------------
extern "C" void kernel_launch(void* const* d_in, const int* in_sizes, int n_in,
                              void* d_out, int out_size) {
    const float* x    = (const float*)d_in[0];
    const int*   ei   = (const int*)d_in[1];
    const float* w    = (const float*)d_in[2];
    const float* att  = (const float*)d_in[3];
    const float* bias = (const float*)d_in[4];
    float* out = (float*)d_out;

    int N = in_sizes[0] / F;
    int E = in_sizes[1] / 2;

    k_gemm<<<(N + BM - 1) / BM, 256>>>(x, w, att, bias, out, N);
    k_edge1<<<(E + 255) / 256, 256>>>(ei, E);
    k_inv<<<(N * H + 255) / 256, 256>>>(N);
    k_edge2<<<(E * 16 + 255) / 256, 256>>>(ei, out, E);
}

// round 8
// speedup vs baseline: 1.5654x; 1.2645x over previous
#include <cuda_runtime.h>
#include <cuda_fp16.h>
#include <cuda_bf16.h>
#include <mma.h>

using namespace nvcuda;

// Problem constants (shapes fixed by the dataset)
#define MAXN 50000
#define MAXE 800000
#define F 128      // input features
#define H 4        // heads
#define C 32       // channels/head  (H*C == F)

// Scratch (device globals; no allocation allowed)
// g_xwh layout is HEAD-INTERLEAVED: g_xwh[n*128 + c*4 + h]  (c=0..31, h=0..3)
__device__ __half g_xwh[MAXN * F];
__device__ float g_ai[MAXN * H];        // att·xw first half  (source role)
__device__ float g_aj[MAXN * H];        // att·xw second half (dest role)
__device__ float g_p[MAXE * H];         // exp(leaky(alpha)) per edge
__device__ float g_segsum[MAXN * H];    // softmax denominator per (row, h)
__device__ float g_inv[MAXN * H];       // 0.25 / (segsum + 1e-16)

// ---------------------------------------------------------------------------
// vector atomic adds (sm_90+)
__device__ __forceinline__ void red_add_v4(float* p, float a, float b, float c, float d) {
    asm volatile("red.global.add.v4.f32 [%0], {%1, %2, %3, %4};"
                 :: "l"(p), "f"(a), "f"(b), "f"(c), "f"(d) : "memory");
}
__device__ __forceinline__ void red_add_v2(float* p, float a, float b) {
    asm volatile("red.global.add.v2.f32 [%0], {%1, %2};"
                 :: "l"(p), "f"(a), "f"(b) : "memory");
}

// ---------------------------------------------------------------------------
// Tensor-core GEMM: xw = x @ W (fp16 HMMA, fp32 accum).
// Block = 64 rows x 128 cols, 8 warps. Both smem tiles use padded strides
// with 4-bank row rotation (LDA=72, LDB=136) so load_matrix_sync is
// conflict-free. Epilogue also:
//   - stores head-interleaved fp16 xw
//   - computes attention half-dots ai/aj
//   - zeroes g_segsum, initializes out = bias
#define BM 64
#define LDA 72           // sA leading dim (halfs): 144B stride, bank-rotating
#define LDB 136          // sB leading dim (halfs): 272B stride, bank-rotating
#define SM_BYTES (32768 + 1024)

__global__ void k_gemm(const float* __restrict__ x, const float* __restrict__ w,
                       const float* __restrict__ att, const float* __restrict__ bias,
                       float* __restrict__ out, int N) {
    __shared__ __align__(16) char smbuf[SM_BYTES];
    __half* sA = (__half*)smbuf;                       // 64*72*2  = 9216 B
    __half* sB = (__half*)(smbuf + 64 * LDA * 2);      // 64*136*2 = 17408 B (ends 26624)
    float*  sC = (float*)smbuf;                        // 64*128*4 = 32768 B (epilogue reuse)
    float*  s_att = (float*)(smbuf + 32768);

    int tid = threadIdx.x;
    int row0 = blockIdx.x * BM;
    int warp = tid >> 5;
    int mt = warp & 3;            // m-tile (16 rows)
    int nb = (warp >> 2) * 64;    // n base (64 cols)

    s_att[tid] = att[tid];

    wmma::fragment<wmma::accumulator, 16, 16, 16, float> acc[4];
#pragma unroll
    for (int t = 0; t < 4; t++) wmma::fill_fragment(acc[t], 0.0f);

    int arow = tid >> 2;          // 0..63
    int aq   = (tid & 3) * 16;    // k-offset within stage
    int brow = tid >> 2;          // 0..63 (k index within stage)
    int bs   = (tid & 3) * 32;    // col segment

#pragma unroll
    for (int k0 = 0; k0 < F; k0 += 64) {
        {
            int grow = row0 + arow;
#pragma unroll
            for (int j = 0; j < 4; j++) {
                float4 v = make_float4(0.f, 0.f, 0.f, 0.f);
                if (grow < N) v = *(const float4*)&x[grow * F + k0 + aq + j * 4];
                __half2 h0 = __floats2half2_rn(v.x, v.y);
                __half2 h1 = __floats2half2_rn(v.z, v.w);
                *(__half2*)&sA[arow * LDA + aq + j * 4]     = h0;
                *(__half2*)&sA[arow * LDA + aq + j * 4 + 2] = h1;
            }
        }
        {
#pragma unroll
            for (int j = 0; j < 8; j++) {
                float4 v = *(const float4*)&w[(k0 + brow) * F + bs + j * 4];
                __half2 h0 = __floats2half2_rn(v.x, v.y);
                __half2 h1 = __floats2half2_rn(v.z, v.w);
                *(__half2*)&sB[brow * LDB + bs + j * 4]     = h0;
                *(__half2*)&sB[brow * LDB + bs + j * 4 + 2] = h1;
            }
        }
        __syncthreads();

#pragma unroll
        for (int kk = 0; kk < 4; kk++) {
            wmma::fragment<wmma::matrix_a, 16, 16, 16, __half, wmma::row_major> fa;
            wmma::load_matrix_sync(fa, &sA[mt * 16 * LDA + kk * 16], LDA);
#pragma unroll
            for (int nt = 0; nt < 4; nt++) {
                wmma::fragment<wmma::matrix_b, 16, 16, 16, __half, wmma::row_major> fb;
                wmma::load_matrix_sync(fb, &sB[kk * 16 * LDB + nb + nt * 16], LDB);
                wmma::mma_sync(acc[nt], fa, fb, acc[nt]);
            }
        }
        __syncthreads();
    }

#pragma unroll
    for (int nt = 0; nt < 4; nt++)
        wmma::store_matrix_sync(&sC[mt * 16 * F + nb + nt * 16], acc[nt], F, wmma::mem_row_major);
    __syncthreads();

    // epilogue: thread t -> (local row = t>>2, channel quarter q = t&3)
    {
        int lrow = tid >> 2;
        int q = tid & 3;
        int grow = row0 + lrow;
        float s1[H], s2[H];
        __half buf[32];
#pragma unroll
        for (int h = 0; h < H; h++) { s1[h] = 0.f; s2[h] = 0.f; }
#pragma unroll
        for (int h = 0; h < H; h++) {
            const float* cr = &sC[lrow * F + h * C + q * 8];
            const float* a1 = &s_att[h * 2 * C + q * 8];
            const float* a2 = a1 + C;
#pragma unroll
            for (int j = 0; j < 8; j++) {
                float v = cr[j];
                s1[h] += v * a1[j];
                s2[h] += v * a2[j];
                buf[j * 4 + h] = __float2half_rn(v);   // interleaved [c][h]
            }
        }
        // butterfly over the 4 q-lanes: elementwise sum per head
#pragma unroll
        for (int h = 0; h < H; h++) {
            s1[h] += __shfl_xor_sync(0xffffffffu, s1[h], 1);
            s1[h] += __shfl_xor_sync(0xffffffffu, s1[h], 2);
            s2[h] += __shfl_xor_sync(0xffffffffu, s2[h], 1);
            s2[h] += __shfl_xor_sync(0xffffffffu, s2[h], 2);
        }
        if (grow < N) {
            // 64B contiguous fp16 store (channels q*8..q*8+7, all heads)
            *(uint4*)&g_xwh[grow * F + q * 32]      = *(uint4*)&buf[0];
            *(uint4*)&g_xwh[grow * F + q * 32 + 8]  = *(uint4*)&buf[8];
            *(uint4*)&g_xwh[grow * F + q * 32 + 16] = *(uint4*)&buf[16];
            *(uint4*)&g_xwh[grow * F + q * 32 + 24] = *(uint4*)&buf[24];
            g_ai[grow * H + q] = s1[q];
            g_aj[grow * H + q] = s2[q];
            g_segsum[grow * H + q] = 0.0f;
            // out = bias  (channels q*8 .. q*8+7)
            float4 b0 = *(const float4*)&bias[q * 8];
            float4 b1 = *(const float4*)&bias[q * 8 + 4];
            *(float4*)&out[grow * C + q * 8]     = b0;
            *(float4*)&out[grow * C + q * 8 + 4] = b1;
        }
    }
}

// ---------------------------------------------------------------------------
// per-edge: p = exp(leaky(a_i[row] + a_j[col])); segsum[row] += p (one v4 red)
// (softmax max-shift skipped: shift-invariant, |alpha| small -> no overflow)
__device__ __forceinline__ float leaky_exp(float a) {
    a = (a >= 0.f) ? a : 0.2f * a;
    return __expf(a);
}

__global__ void k_edge1(const int* __restrict__ ei, int E) {
    int e = blockIdx.x * blockDim.x + threadIdx.x;
    if (e >= E) return;
    int r = ei[e];
    int c = ei[E + e];
    float4 ai = *(const float4*)&g_ai[r * H];
    float4 aj = *(const float4*)&g_aj[c * H];
    float4 p;
    p.x = leaky_exp(ai.x + aj.x);
    p.y = leaky_exp(ai.y + aj.y);
    p.z = leaky_exp(ai.z + aj.z);
    p.w = leaky_exp(ai.w + aj.w);
    *(float4*)&g_p[e * H] = p;
    red_add_v4(&g_segsum[r * H], p.x, p.y, p.z, p.w);
}

// ---------------------------------------------------------------------------
// inv[n,h] = 0.25 / (segsum[n,h] + 1e-16)   (folds head-mean factor)
__global__ void k_inv(int N) {
    int t = blockIdx.x * blockDim.x + threadIdx.x;
    if (t >= N * H) return;
    g_inv[t] = 0.25f / (g_segsum[t] + 1e-16f);
}

// ---------------------------------------------------------------------------
// aggregation: 16 lanes per edge, 2 edges per warp.
// Lane l covers output channels 2l, 2l+1: loads ONE uint4 (16B) of the
// head-interleaved row = {c0:h0..h3, c1:h0..h3}, folds heads, red.v2 out.
__global__ void k_edge2(const int* __restrict__ ei, float* __restrict__ out, int E) {
    int gt = blockIdx.x * blockDim.x + threadIdx.x;
    int e = gt >> 4;
    if (e >= E) return;
    int l = gt & 15;

    int r = __ldg(&ei[e]);
    int c = __ldg(&ei[E + e]);

    float4 p = *(const float4*)&g_p[e * H];
    float4 iv = *(const float4*)&g_inv[r * H];
    float w0 = p.x * iv.x;
    float w1 = p.y * iv.y;
    float w2 = p.z * iv.z;
    float w3 = p.w * iv.w;

    uint4 u = *(const uint4*)&g_xwh[r * F + l * 8];   // 8 halfs, 16B coalesced
    float2 c0a = __half22float2(*reinterpret_cast<__half2*>(&u.x));  // c0: h0,h1
    float2 c0b = __half22float2(*reinterpret_cast<__half2*>(&u.y));  // c0: h2,h3
    float2 c1a = __half22float2(*reinterpret_cast<__half2*>(&u.z));  // c1: h0,h1
    float2 c1b = __half22float2(*reinterpret_cast<__half2*>(&u.w));  // c1: h2,h3

    float m0 = w0 * c0a.x + w1 * c0a.y + w2 * c0b.x + w3 * c0b.y;
    float m1 = w0 * c1a.x + w1 * c1a.y + w2 * c1b.x + w3 * c1b.y;

    red_add_v2(&out[c * C + l * 2], m0, m1);
}

// ---------------------------------------------------------------------------
extern "C" void kernel_launch(void* const* d_in, const int* in_sizes, int n_in,
                              void* d_out, int out_size) {
    const float* x    = (const float*)d_in[0];
    const int*   ei   = (const int*)d_in[1];
    const float* w    = (const float*)d_in[2];
    const float* att  = (const float*)d_in[3];
    const float* bias = (const float*)d_in[4];
    float* out = (float*)d_out;

    int N = in_sizes[0] / F;
    int E = in_sizes[1] / 2;

    k_gemm<<<(N + BM - 1) / BM, 256>>>(x, w, att, bias, out, N);
    k_edge1<<<(E + 255) / 256, 256>>>(ei, E);
    k_inv<<<(N * H + 255) / 256, 256>>>(N);
    k_edge2<<<(E * 16 + 255) / 256, 256>>>(ei, out, E);
}

// round 9
// speedup vs baseline: 1.7738x; 1.1331x over previous
#include <cuda_runtime.h>
#include <cuda_fp16.h>
#include <cuda_bf16.h>
#include <mma.h>

using namespace nvcuda;

// Problem constants (shapes fixed by the dataset)
#define MAXN 50000
#define MAXE 800000
#define F 128      // input features
#define H 4        // heads
#define C 32       // channels/head  (H*C == F)

// Scratch (device globals; no allocation allowed)
// g_xwh layout is HEAD-INTERLEAVED: g_xwh[n*128 + c*4 + h]  (c=0..31, h=0..3)
__device__ __half g_xwh[MAXN * F];
__device__ float g_ai[MAXN * H];        // att·xw first half  (source role)
__device__ float g_aj[MAXN * H];        // att·xw second half (dest role)
__device__ float g_p[MAXE * H];         // exp(leaky(alpha)) per edge
__device__ float g_segsum[MAXN * H];    // softmax denominator per (row, h)
__device__ float g_inv[MAXN * H];       // 0.25 / (segsum + 1e-16)

// ---------------------------------------------------------------------------
// vector atomic adds (sm_90+)
__device__ __forceinline__ void red_add_v4(float* p, float a, float b, float c, float d) {
    asm volatile("red.global.add.v4.f32 [%0], {%1, %2, %3, %4};"
                 :: "l"(p), "f"(a), "f"(b), "f"(c), "f"(d) : "memory");
}

// ---------------------------------------------------------------------------
// Tensor-core GEMM: xw = x @ W (fp16 HMMA, fp32 accum).
// Block = 64 rows x 128 cols, 8 warps. Both smem tiles use padded strides
// with 4-bank row rotation (LDA=72, LDB=136) so load_matrix_sync is
// conflict-free. Epilogue also:
//   - stores head-interleaved fp16 xw
//   - computes attention half-dots ai/aj
//   - zeroes g_segsum, initializes out = bias
#define BM 64
#define LDA 72           // sA leading dim (halfs): 144B stride, bank-rotating
#define LDB 136          // sB leading dim (halfs): 272B stride, bank-rotating
#define SM_BYTES (32768 + 1024)

__global__ void k_gemm(const float* __restrict__ x, const float* __restrict__ w,
                       const float* __restrict__ att, const float* __restrict__ bias,
                       float* __restrict__ out, int N) {
    __shared__ __align__(16) char smbuf[SM_BYTES];
    __half* sA = (__half*)smbuf;                       // 64*72*2  = 9216 B
    __half* sB = (__half*)(smbuf + 64 * LDA * 2);      // 64*136*2 = 17408 B (ends 26624)
    float*  sC = (float*)smbuf;                        // 64*128*4 = 32768 B (epilogue reuse)
    float*  s_att = (float*)(smbuf + 32768);

    int tid = threadIdx.x;
    int row0 = blockIdx.x * BM;
    int warp = tid >> 5;
    int mt = warp & 3;            // m-tile (16 rows)
    int nb = (warp >> 2) * 64;    // n base (64 cols)

    s_att[tid] = att[tid];

    wmma::fragment<wmma::accumulator, 16, 16, 16, float> acc[4];
#pragma unroll
    for (int t = 0; t < 4; t++) wmma::fill_fragment(acc[t], 0.0f);

    int arow = tid >> 2;          // 0..63
    int aq   = (tid & 3) * 16;    // k-offset within stage
    int brow = tid >> 2;          // 0..63 (k index within stage)
    int bs   = (tid & 3) * 32;    // col segment

#pragma unroll
    for (int k0 = 0; k0 < F; k0 += 64) {
        {
            int grow = row0 + arow;
#pragma unroll
            for (int j = 0; j < 4; j++) {
                float4 v = make_float4(0.f, 0.f, 0.f, 0.f);
                if (grow < N) v = *(const float4*)&x[grow * F + k0 + aq + j * 4];
                __half2 h0 = __floats2half2_rn(v.x, v.y);
                __half2 h1 = __floats2half2_rn(v.z, v.w);
                *(__half2*)&sA[arow * LDA + aq + j * 4]     = h0;
                *(__half2*)&sA[arow * LDA + aq + j * 4 + 2] = h1;
            }
        }
        {
#pragma unroll
            for (int j = 0; j < 8; j++) {
                float4 v = *(const float4*)&w[(k0 + brow) * F + bs + j * 4];
                __half2 h0 = __floats2half2_rn(v.x, v.y);
                __half2 h1 = __floats2half2_rn(v.z, v.w);
                *(__half2*)&sB[brow * LDB + bs + j * 4]     = h0;
                *(__half2*)&sB[brow * LDB + bs + j * 4 + 2] = h1;
            }
        }
        __syncthreads();

#pragma unroll
        for (int kk = 0; kk < 4; kk++) {
            wmma::fragment<wmma::matrix_a, 16, 16, 16, __half, wmma::row_major> fa;
            wmma::load_matrix_sync(fa, &sA[mt * 16 * LDA + kk * 16], LDA);
#pragma unroll
            for (int nt = 0; nt < 4; nt++) {
                wmma::fragment<wmma::matrix_b, 16, 16, 16, __half, wmma::row_major> fb;
                wmma::load_matrix_sync(fb, &sB[kk * 16 * LDB + nb + nt * 16], LDB);
                wmma::mma_sync(acc[nt], fa, fb, acc[nt]);
            }
        }
        __syncthreads();
    }

#pragma unroll
    for (int nt = 0; nt < 4; nt++)
        wmma::store_matrix_sync(&sC[mt * 16 * F + nb + nt * 16], acc[nt], F, wmma::mem_row_major);
    __syncthreads();

    // epilogue: thread t -> (local row = t>>2, channel quarter q = t&3)
    {
        int lrow = tid >> 2;
        int q = tid & 3;
        int grow = row0 + lrow;
        float s1[H], s2[H];
        __half buf[32];
#pragma unroll
        for (int h = 0; h < H; h++) { s1[h] = 0.f; s2[h] = 0.f; }
#pragma unroll
        for (int h = 0; h < H; h++) {
            const float* cr = &sC[lrow * F + h * C + q * 8];
            const float* a1 = &s_att[h * 2 * C + q * 8];
            const float* a2 = a1 + C;
#pragma unroll
            for (int j = 0; j < 8; j++) {
                float v = cr[j];
                s1[h] += v * a1[j];
                s2[h] += v * a2[j];
                buf[j * 4 + h] = __float2half_rn(v);   // interleaved [c][h]
            }
        }
        // butterfly over the 4 q-lanes: elementwise sum per head
#pragma unroll
        for (int h = 0; h < H; h++) {
            s1[h] += __shfl_xor_sync(0xffffffffu, s1[h], 1);
            s1[h] += __shfl_xor_sync(0xffffffffu, s1[h], 2);
            s2[h] += __shfl_xor_sync(0xffffffffu, s2[h], 1);
            s2[h] += __shfl_xor_sync(0xffffffffu, s2[h], 2);
        }
        if (grow < N) {
            // 64B contiguous fp16 store (channels q*8..q*8+7, all heads)
            *(uint4*)&g_xwh[grow * F + q * 32]      = *(uint4*)&buf[0];
            *(uint4*)&g_xwh[grow * F + q * 32 + 8]  = *(uint4*)&buf[8];
            *(uint4*)&g_xwh[grow * F + q * 32 + 16] = *(uint4*)&buf[16];
            *(uint4*)&g_xwh[grow * F + q * 32 + 24] = *(uint4*)&buf[24];
            g_ai[grow * H + q] = s1[q];
            g_aj[grow * H + q] = s2[q];
            g_segsum[grow * H + q] = 0.0f;
            // out = bias  (channels q*8 .. q*8+7)
            float4 b0 = *(const float4*)&bias[q * 8];
            float4 b1 = *(const float4*)&bias[q * 8 + 4];
            *(float4*)&out[grow * C + q * 8]     = b0;
            *(float4*)&out[grow * C + q * 8 + 4] = b1;
        }
    }
}

// ---------------------------------------------------------------------------
// per-edge: p = exp(leaky(a_i[row] + a_j[col])); segsum[row] += p (one v4 red)
// (softmax max-shift skipped: shift-invariant, |alpha| small -> no overflow)
__device__ __forceinline__ float leaky_exp(float a) {
    a = (a >= 0.f) ? a : 0.2f * a;
    return __expf(a);
}

__global__ void k_edge1(const int* __restrict__ ei, int E) {
    int e = blockIdx.x * blockDim.x + threadIdx.x;
    if (e >= E) return;
    int r = ei[e];
    int c = ei[E + e];
    float4 ai = *(const float4*)&g_ai[r * H];
    float4 aj = *(const float4*)&g_aj[c * H];
    float4 p;
    p.x = leaky_exp(ai.x + aj.x);
    p.y = leaky_exp(ai.y + aj.y);
    p.z = leaky_exp(ai.z + aj.z);
    p.w = leaky_exp(ai.w + aj.w);
    *(float4*)&g_p[e * H] = p;
    red_add_v4(&g_segsum[r * H], p.x, p.y, p.z, p.w);
}

// ---------------------------------------------------------------------------
// inv[n,h] = 0.25 / (segsum[n,h] + 1e-16)   (folds head-mean factor)
__global__ void k_inv(int N) {
    int t = blockIdx.x * blockDim.x + threadIdx.x;
    if (t >= N * H) return;
    g_inv[t] = 0.25f / (g_segsum[t] + 1e-16f);
}

// ---------------------------------------------------------------------------
// aggregation: 8 lanes per edge, 4 edges per warp.
// Lane l covers output channels 4l..4l+3: loads 32B (2x uint4) of the
// head-interleaved row, folds heads, ONE red.v4 out (16B per lane-op --
// halves REDG lane-op count vs the 16-lane red.v2 scheme).
__global__ void k_edge2(const int* __restrict__ ei, float* __restrict__ out, int E) {
    int gt = blockIdx.x * blockDim.x + threadIdx.x;
    int e = gt >> 3;
    if (e >= E) return;
    int l = gt & 7;

    int r = __ldg(&ei[e]);
    int c = __ldg(&ei[E + e]);

    float4 p = *(const float4*)&g_p[e * H];
    float4 iv = *(const float4*)&g_inv[r * H];
    float w0 = p.x * iv.x;
    float w1 = p.y * iv.y;
    float w2 = p.z * iv.z;
    float w3 = p.w * iv.w;

    // channels 4l..4l+3 -> halfs [16l .. 16l+15] (32B contiguous)
    const __half* xr = &g_xwh[r * F + l * 16];
    uint4 ua = *(const uint4*)&xr[0];   // c0:{h0..h3}, c1:{h0..h3}
    uint4 ub = *(const uint4*)&xr[8];   // c2:{h0..h3}, c3:{h0..h3}

    float2 c0a = __half22float2(*reinterpret_cast<__half2*>(&ua.x));
    float2 c0b = __half22float2(*reinterpret_cast<__half2*>(&ua.y));
    float2 c1a = __half22float2(*reinterpret_cast<__half2*>(&ua.z));
    float2 c1b = __half22float2(*reinterpret_cast<__half2*>(&ua.w));
    float2 c2a = __half22float2(*reinterpret_cast<__half2*>(&ub.x));
    float2 c2b = __half22float2(*reinterpret_cast<__half2*>(&ub.y));
    float2 c3a = __half22float2(*reinterpret_cast<__half2*>(&ub.z));
    float2 c3b = __half22float2(*reinterpret_cast<__half2*>(&ub.w));

    float m0 = w0 * c0a.x + w1 * c0a.y + w2 * c0b.x + w3 * c0b.y;
    float m1 = w0 * c1a.x + w1 * c1a.y + w2 * c1b.x + w3 * c1b.y;
    float m2 = w0 * c2a.x + w1 * c2a.y + w2 * c2b.x + w3 * c2b.y;
    float m3 = w0 * c3a.x + w1 * c3a.y + w2 * c3b.x + w3 * c3b.y;

    red_add_v4(&out[c * C + l * 4], m0, m1, m2, m3);
}

// ---------------------------------------------------------------------------
extern "C" void kernel_launch(void* const* d_in, const int* in_sizes, int n_in,
                              void* d_out, int out_size) {
    const float* x    = (const float*)d_in[0];
    const int*   ei   = (const int*)d_in[1];
    const float* w    = (const float*)d_in[2];
    const float* att  = (const float*)d_in[3];
    const float* bias = (const float*)d_in[4];
    float* out = (float*)d_out;

    int N = in_sizes[0] / F;
    int E = in_sizes[1] / 2;

    k_gemm<<<(N + BM - 1) / BM, 256>>>(x, w, att, bias, out, N);
    k_edge1<<<(E + 255) / 256, 256>>>(ei, E);
    k_inv<<<(N * H + 255) / 256, 256>>>(N);
    k_edge2<<<(E * 8 + 255) / 256, 256>>>(ei, out, E);
}

// round 10
// speedup vs baseline: 1.7847x; 1.0062x over previous
#include <cuda_runtime.h>
#include <cuda_fp16.h>
#include <cuda_bf16.h>
#include <mma.h>

using namespace nvcuda;

// Problem constants (shapes fixed by the dataset)
#define MAXN 50000
#define MAXE 800000
#define F 128      // input features
#define H 4        // heads
#define C 32       // channels/head  (H*C == F)

// Scratch (device globals; no allocation allowed)
// g_xwh layout is HEAD-INTERLEAVED: g_xwh[n*128 + c*4 + h]  (c=0..31, h=0..3)
__device__ __half g_xwh[MAXN * F];
__device__ float g_ai[MAXN * H];        // att·xw first half  (source role)
__device__ float g_aj[MAXN * H];        // att·xw second half (dest role)
__device__ __half2 g_ph[MAXE * 2];      // exp(leaky(alpha)) per edge, fp16 packed
__device__ float g_segsum[MAXN * H];    // softmax denominator per (row, h)
__device__ float g_inv[MAXN * H];       // 0.25 / (segsum + 1e-16)

// ---------------------------------------------------------------------------
// vector atomic adds (sm_90+)
__device__ __forceinline__ void red_add_v4(float* p, float a, float b, float c, float d) {
    asm volatile("red.global.add.v4.f32 [%0], {%1, %2, %3, %4};"
                 :: "l"(p), "f"(a), "f"(b), "f"(c), "f"(d) : "memory");
}

// ---------------------------------------------------------------------------
// Tensor-core GEMM: xw = x @ W (fp16 HMMA, fp32 accum).
// Block = 64 rows x 128 cols, 8 warps. Both smem tiles use padded strides
// with 4-bank row rotation (LDA=72, LDB=136) so load_matrix_sync is
// conflict-free. Epilogue also:
//   - stores head-interleaved fp16 xw
//   - computes attention half-dots ai/aj
//   - zeroes g_segsum, initializes out = bias
#define BM 64
#define LDA 72           // sA leading dim (halfs): 144B stride, bank-rotating
#define LDB 136          // sB leading dim (halfs): 272B stride, bank-rotating
#define SM_BYTES (32768 + 1024)

__global__ void k_gemm(const float* __restrict__ x, const float* __restrict__ w,
                       const float* __restrict__ att, const float* __restrict__ bias,
                       float* __restrict__ out, int N) {
    __shared__ __align__(16) char smbuf[SM_BYTES];
    __half* sA = (__half*)smbuf;                       // 64*72*2  = 9216 B
    __half* sB = (__half*)(smbuf + 64 * LDA * 2);      // 64*136*2 = 17408 B (ends 26624)
    float*  sC = (float*)smbuf;                        // 64*128*4 = 32768 B (epilogue reuse)
    float*  s_att = (float*)(smbuf + 32768);

    int tid = threadIdx.x;
    int row0 = blockIdx.x * BM;
    int warp = tid >> 5;
    int mt = warp & 3;            // m-tile (16 rows)
    int nb = (warp >> 2) * 64;    // n base (64 cols)

    s_att[tid] = att[tid];

    wmma::fragment<wmma::accumulator, 16, 16, 16, float> acc[4];
#pragma unroll
    for (int t = 0; t < 4; t++) wmma::fill_fragment(acc[t], 0.0f);

    int arow = tid >> 2;          // 0..63
    int aq   = (tid & 3) * 16;    // k-offset within stage
    int brow = tid >> 2;          // 0..63 (k index within stage)
    int bs   = (tid & 3) * 32;    // col segment

#pragma unroll
    for (int k0 = 0; k0 < F; k0 += 64) {
        {
            int grow = row0 + arow;
#pragma unroll
            for (int j = 0; j < 4; j++) {
                float4 v = make_float4(0.f, 0.f, 0.f, 0.f);
                if (grow < N) v = *(const float4*)&x[grow * F + k0 + aq + j * 4];
                __half2 h0 = __floats2half2_rn(v.x, v.y);
                __half2 h1 = __floats2half2_rn(v.z, v.w);
                *(__half2*)&sA[arow * LDA + aq + j * 4]     = h0;
                *(__half2*)&sA[arow * LDA + aq + j * 4 + 2] = h1;
            }
        }
        {
#pragma unroll
            for (int j = 0; j < 8; j++) {
                float4 v = *(const float4*)&w[(k0 + brow) * F + bs + j * 4];
                __half2 h0 = __floats2half2_rn(v.x, v.y);
                __half2 h1 = __floats2half2_rn(v.z, v.w);
                *(__half2*)&sB[brow * LDB + bs + j * 4]     = h0;
                *(__half2*)&sB[brow * LDB + bs + j * 4 + 2] = h1;
            }
        }
        __syncthreads();

#pragma unroll
        for (int kk = 0; kk < 4; kk++) {
            wmma::fragment<wmma::matrix_a, 16, 16, 16, __half, wmma::row_major> fa;
            wmma::load_matrix_sync(fa, &sA[mt * 16 * LDA + kk * 16], LDA);
#pragma unroll
            for (int nt = 0; nt < 4; nt++) {
                wmma::fragment<wmma::matrix_b, 16, 16, 16, __half, wmma::row_major> fb;
                wmma::load_matrix_sync(fb, &sB[kk * 16 * LDB + nb + nt * 16], LDB);
                wmma::mma_sync(acc[nt], fa, fb, acc[nt]);
            }
        }
        __syncthreads();
    }

#pragma unroll
    for (int nt = 0; nt < 4; nt++)
        wmma::store_matrix_sync(&sC[mt * 16 * F + nb + nt * 16], acc[nt], F, wmma::mem_row_major);
    __syncthreads();

    // epilogue: thread t -> (local row = t>>2, channel quarter q = t&3)
    {
        int lrow = tid >> 2;
        int q = tid & 3;
        int grow = row0 + lrow;
        float s1[H], s2[H];
        __half buf[32];
#pragma unroll
        for (int h = 0; h < H; h++) { s1[h] = 0.f; s2[h] = 0.f; }
#pragma unroll
        for (int h = 0; h < H; h++) {
            const float* cr = &sC[lrow * F + h * C + q * 8];
            const float* a1 = &s_att[h * 2 * C + q * 8];
            const float* a2 = a1 + C;
#pragma unroll
            for (int j = 0; j < 8; j++) {
                float v = cr[j];
                s1[h] += v * a1[j];
                s2[h] += v * a2[j];
                buf[j * 4 + h] = __float2half_rn(v);   // interleaved [c][h]
            }
        }
        // butterfly over the 4 q-lanes: elementwise sum per head
#pragma unroll
        for (int h = 0; h < H; h++) {
            s1[h] += __shfl_xor_sync(0xffffffffu, s1[h], 1);
            s1[h] += __shfl_xor_sync(0xffffffffu, s1[h], 2);
            s2[h] += __shfl_xor_sync(0xffffffffu, s2[h], 1);
            s2[h] += __shfl_xor_sync(0xffffffffu, s2[h], 2);
        }
        if (grow < N) {
            // 64B contiguous fp16 store (channels q*8..q*8+7, all heads)
            *(uint4*)&g_xwh[grow * F + q * 32]      = *(uint4*)&buf[0];
            *(uint4*)&g_xwh[grow * F + q * 32 + 8]  = *(uint4*)&buf[8];
            *(uint4*)&g_xwh[grow * F + q * 32 + 16] = *(uint4*)&buf[16];
            *(uint4*)&g_xwh[grow * F + q * 32 + 24] = *(uint4*)&buf[24];
            g_ai[grow * H + q] = s1[q];
            g_aj[grow * H + q] = s2[q];
            g_segsum[grow * H + q] = 0.0f;
            // out = bias  (channels q*8 .. q*8+7)
            float4 b0 = *(const float4*)&bias[q * 8];
            float4 b1 = *(const float4*)&bias[q * 8 + 4];
            *(float4*)&out[grow * C + q * 8]     = b0;
            *(float4*)&out[grow * C + q * 8 + 4] = b1;
        }
    }
}

// ---------------------------------------------------------------------------
// fast exp on the FMA/ALU pipes (no MUFU): exp(x) = 2^(x*log2e),
// 2^t = 2^floor(t) * poly(frac(t)), exponent added via integer bit trick.
// Max rel err ~1e-6 over the relevant range; inputs clamped to avoid
// exponent overflow in the bit trick.
__device__ __forceinline__ float fast_exp(float x) {
    float t = x * 1.4426950408889634f;
    t = fminf(fmaxf(t, -80.0f), 80.0f);
    float fi = floorf(t);
    float f = t - fi;
    // degree-4 minimax-ish poly for 2^f, f in [0,1)
    float p = 1.3534581508e-2f;
    p = fmaf(p, f, 5.2011464331e-2f);
    p = fmaf(p, f, 2.4144275732e-1f);
    p = fmaf(p, f, 6.9300613463e-1f);
    p = fmaf(p, f, 9.9999989038e-1f);
    return __int_as_float(__float_as_int(p) + ((int)fi << 23));
}

__device__ __forceinline__ float leaky_exp(float a) {
    a = (a >= 0.f) ? a : 0.2f * a;
    return fast_exp(a);
}

// ---------------------------------------------------------------------------
// per-edge: p = exp(leaky(a_i[row] + a_j[col])); segsum[row] += p (one v4 red)
// p stored fp16-packed (8B). (softmax max-shift skipped: shift-invariant,
// |alpha| small -> no overflow)
__global__ void k_edge1(const int* __restrict__ ei, int E) {
    int e = blockIdx.x * blockDim.x + threadIdx.x;
    if (e >= E) return;
    int r = ei[e];
    int c = ei[E + e];
    float4 ai = *(const float4*)&g_ai[r * H];
    float4 aj = *(const float4*)&g_aj[c * H];
    float px = leaky_exp(ai.x + aj.x);
    float py = leaky_exp(ai.y + aj.y);
    float pz = leaky_exp(ai.z + aj.z);
    float pw = leaky_exp(ai.w + aj.w);
    __half2 h01 = __floats2half2_rn(px, py);
    __half2 h23 = __floats2half2_rn(pz, pw);
    uint2 pk;
    pk.x = *reinterpret_cast<unsigned*>(&h01);
    pk.y = *reinterpret_cast<unsigned*>(&h23);
    *(uint2*)&g_ph[e * 2] = pk;
    red_add_v4(&g_segsum[r * H], px, py, pz, pw);
}

// ---------------------------------------------------------------------------
// inv[n,h] = 0.25 / (segsum[n,h] + 1e-16)   (folds head-mean factor)
__global__ void k_inv(int N) {
    int t = blockIdx.x * blockDim.x + threadIdx.x;
    if (t >= N * H) return;
    g_inv[t] = 0.25f / (g_segsum[t] + 1e-16f);
}

// ---------------------------------------------------------------------------
// aggregation: 8 lanes per edge, 4 edges per warp.
// Lane l covers output channels 4l..4l+3: loads 32B (2x uint4) of the
// head-interleaved row, folds heads, ONE red.v4 out (16B per lane-op).
__global__ void k_edge2(const int* __restrict__ ei, float* __restrict__ out, int E) {
    int gt = blockIdx.x * blockDim.x + threadIdx.x;
    int e = gt >> 3;
    if (e >= E) return;
    int l = gt & 7;

    int r = __ldg(&ei[e]);
    int c = __ldg(&ei[E + e]);

    uint2 pk = *(const uint2*)&g_ph[e * 2];   // 8B broadcast load
    float2 p01 = __half22float2(*reinterpret_cast<__half2*>(&pk.x));
    float2 p23 = __half22float2(*reinterpret_cast<__half2*>(&pk.y));
    float4 iv = *(const float4*)&g_inv[r * H];
    float w0 = p01.x * iv.x;
    float w1 = p01.y * iv.y;
    float w2 = p23.x * iv.z;
    float w3 = p23.y * iv.w;

    // channels 4l..4l+3 -> halfs [16l .. 16l+15] (32B contiguous)
    const __half* xr = &g_xwh[r * F + l * 16];
    uint4 ua = *(const uint4*)&xr[0];   // c0:{h0..h3}, c1:{h0..h3}
    uint4 ub = *(const uint4*)&xr[8];   // c2:{h0..h3}, c3:{h0..h3}

    float2 c0a = __half22float2(*reinterpret_cast<__half2*>(&ua.x));
    float2 c0b = __half22float2(*reinterpret_cast<__half2*>(&ua.y));
    float2 c1a = __half22float2(*reinterpret_cast<__half2*>(&ua.z));
    float2 c1b = __half22float2(*reinterpret_cast<__half2*>(&ua.w));
    float2 c2a = __half22float2(*reinterpret_cast<__half2*>(&ub.x));
    float2 c2b = __half22float2(*reinterpret_cast<__half2*>(&ub.y));
    float2 c3a = __half22float2(*reinterpret_cast<__half2*>(&ub.z));
    float2 c3b = __half22float2(*reinterpret_cast<__half2*>(&ub.w));

    float m0 = w0 * c0a.x + w1 * c0a.y + w2 * c0b.x + w3 * c0b.y;
    float m1 = w0 * c1a.x + w1 * c1a.y + w2 * c1b.x + w3 * c1b.y;
    float m2 = w0 * c2a.x + w1 * c2a.y + w2 * c2b.x + w3 * c2b.y;
    float m3 = w0 * c3a.x + w1 * c3a.y + w2 * c3b.x + w3 * c3b.y;

    red_add_v4(&out[c * C + l * 4], m0, m1, m2, m3);
}

// ---------------------------------------------------------------------------
extern "C" void kernel_launch(void* const* d_in, const int* in_sizes, int n_in,
                              void* d_out, int out_size) {
    const float* x    = (const float*)d_in[0];
    const int*   ei   = (const int*)d_in[1];
    const float* w    = (const float*)d_in[2];
    const float* att  = (const float*)d_in[3];
    const float* bias = (const float*)d_in[4];
    float* out = (float*)d_out;

    int N = in_sizes[0] / F;
    int E = in_sizes[1] / 2;

    k_gemm<<<(N + BM - 1) / BM, 256>>>(x, w, att, bias, out, N);
    k_edge1<<<(E + 255) / 256, 256>>>(ei, E);
    k_inv<<<(N * H + 255) / 256, 256>>>(N);
    k_edge2<<<(E * 8 + 255) / 256, 256>>>(ei, out, E);
}